// round 5
// baseline (speedup 1.0000x reference)
#include <cuda_runtime.h>
#include <cuda_bf16.h>
#include <math.h>

// PLIF neuron scan: x[B,T,C] -> spikes[B,T,C]
//   v = v*sigmoid(decay_param[c]) + x[b,t,c]; s = (v > 0.5); v -= 0.5*s
// B=128, T=256, C=2048.
//
// R5: R1 geometry (block=256, grid=256, 16 warps/SM — best so far) with
// prefetch ring deepened PF 8->16 to double in-flight DRAM bytes/SM
// (~65KB -> ~131KB). Register cap set via launch_bounds(256,2) = 128
// regs/thread so the 16-float4 ring (~95-100 regs total) cannot spill
// (R3's failure: 64-reg cap -> local-memory spill, DRAM 78.5% -> 52.8%).
// A/B evidence R1 vs R4: dur tracks in-flight bytes, not block balance.

#define T_STEPS 256
#define C_CH    2048
#define GROUPS  (C_CH / 4)   // 512 float4 groups per channel dim
#define PF      16           // prefetch depth; ring = 64 regs

static_assert((T_STEPS - PF) % PF == 0, "steady loop must be multiple of PF");

__global__ __launch_bounds__(256, 2)   // reg cap 128/thread — ring fits
void plif_scan_kernel(const float* __restrict__ x,
                      const float* __restrict__ decay_param,
                      float* __restrict__ out)
{
    const int tid = blockIdx.x * blockDim.x + threadIdx.x;  // 0 .. 65535
    const int g   = tid & (GROUPS - 1);   // float4 group within C
    const int b   = tid >> 9;             // batch row (tid / 512)

    // Per-channel decay = sigmoid(decay_param). Computed once; IEEE expf to
    // avoid compounded drift over 256 recurrence steps.
    const float4 dp = reinterpret_cast<const float4*>(decay_param)[g];
    const float d0 = 1.0f / (1.0f + expf(-dp.x));
    const float d1 = 1.0f / (1.0f + expf(-dp.y));
    const float d2 = 1.0f / (1.0f + expf(-dp.z));
    const float d3 = 1.0f / (1.0f + expf(-dp.w));

    const float4* xp = reinterpret_cast<const float4*>(x)
                     + (size_t)b * (T_STEPS * GROUPS) + g;
    float4*       op = reinterpret_cast<float4*>(out)
                     + (size_t)b * (T_STEPS * GROUPS) + g;

    float v0 = 0.0f, v1 = 0.0f, v2 = 0.0f, v3 = 0.0f;

    // Prime the ring: PF independent in-flight LDG.128 per thread.
    float4 buf[PF];
#pragma unroll
    for (int i = 0; i < PF; i++)
        buf[i] = __ldcs(xp + i * GROUPS);

#define PLIF_STEP(CUR)                                                  \
    do {                                                                \
        v0 = fmaf(v0, d0, (CUR).x);                                     \
        v1 = fmaf(v1, d1, (CUR).y);                                     \
        v2 = fmaf(v2, d2, (CUR).z);                                     \
        v3 = fmaf(v3, d3, (CUR).w);                                     \
        const float s0 = (v0 > 0.5f) ? 1.0f : 0.0f;                     \
        const float s1 = (v1 > 0.5f) ? 1.0f : 0.0f;                     \
        const float s2 = (v2 > 0.5f) ? 1.0f : 0.0f;                     \
        const float s3 = (v3 > 0.5f) ? 1.0f : 0.0f;                     \
        v0 = fmaf(s0, -0.5f, v0);                                       \
        v1 = fmaf(s1, -0.5f, v1);                                       \
        v2 = fmaf(s2, -0.5f, v2);                                       \
        v3 = fmaf(s3, -0.5f, v3);                                       \
        __stcs(op + t * GROUPS, make_float4(s0, s1, s2, s3));           \
    } while (0)

    // Steady state: 240 iters = 15 * 16; full unroll-16 keeps the ring
    // index a compile-time constant (pure registers, no local memory).
#pragma unroll 16
    for (int t = 0; t < T_STEPS - PF; t++) {
        const float4 cur = buf[t & (PF - 1)];
        buf[t & (PF - 1)] = __ldcs(xp + (t + PF) * GROUPS);
        PLIF_STEP(cur);
    }

    // Epilogue: drain the ring, no further loads.
#pragma unroll
    for (int t = T_STEPS - PF; t < T_STEPS; t++) {
        const float4 cur = buf[t & (PF - 1)];
        PLIF_STEP(cur);
    }
#undef PLIF_STEP
}

extern "C" void kernel_launch(void* const* d_in, const int* in_sizes, int n_in,
                              void* d_out, int out_size)
{
    const float* x  = (const float*)d_in[0];        // [128, 256, 2048]
    const float* dp = (const float*)d_in[1];        // [2048]
    float*       o  = (float*)d_out;                // [128, 256, 2048]

    const int total_threads = 128 * GROUPS;          // 65536
    const int block = 256;
    const int grid  = total_threads / block;         // 256
    plif_scan_kernel<<<grid, block>>>(x, dp, o);
}

// round 6
// speedup vs baseline: 1.0024x; 1.0024x over previous
#include <cuda_runtime.h>
#include <cuda_bf16.h>
#include <math.h>

// PLIF neuron scan: x[B,T,C] -> spikes[B,T,C]
//   v = v*sigmoid(decay_param[c]) + x[b,t,c]; s = (v > 0.5); v -= 0.5*s
// B=128, T=256, C=2048.
//
// R6: occupancy experiment. float4 -> float2 lanes: 131072 threads,
// grid 512 x block 256 => 3-4 blocks/SM (24-32 warps, occ ~40% vs 20.5%).
// PF stays 8 (per-thread queue depth proven optimal in R1/R5 A/B); total
// in-flight bytes/SM preserved via 2x warps of LDG.64. Ring = 16 regs,
// body ~40 regs, launch_bounds(256,4) = 64-reg cap -> no spill.

#define T_STEPS 256
#define C_CH    2048
#define GROUPS2 (C_CH / 2)   // 1024 float2 groups per channel dim
#define PF      8            // prefetch depth (power of 2)

static_assert((T_STEPS - PF) % PF == 0, "steady loop must be multiple of PF");

__global__ __launch_bounds__(256, 4)   // 64-reg cap; body ~40 regs
void plif_scan_kernel(const float* __restrict__ x,
                      const float* __restrict__ decay_param,
                      float* __restrict__ out)
{
    const int tid = blockIdx.x * blockDim.x + threadIdx.x;  // 0 .. 131071
    const int g   = tid & (GROUPS2 - 1);  // float2 group within C
    const int b   = tid >> 10;            // batch row (tid / 1024)

    // Per-channel decay = sigmoid(decay_param). Computed once; IEEE expf to
    // avoid compounded drift over 256 recurrence steps.
    const float2 dp = reinterpret_cast<const float2*>(decay_param)[g];
    const float d0 = 1.0f / (1.0f + expf(-dp.x));
    const float d1 = 1.0f / (1.0f + expf(-dp.y));

    const float2* xp = reinterpret_cast<const float2*>(x)
                     + (size_t)b * (T_STEPS * GROUPS2) + g;
    float2*       op = reinterpret_cast<float2*>(out)
                     + (size_t)b * (T_STEPS * GROUPS2) + g;

    float v0 = 0.0f, v1 = 0.0f;

    // Prime the ring: PF independent in-flight LDG.64 per thread.
    float2 buf[PF];
#pragma unroll
    for (int i = 0; i < PF; i++)
        buf[i] = __ldcs(xp + i * GROUPS2);

#define PLIF_STEP(CUR)                                                  \
    do {                                                                \
        v0 = fmaf(v0, d0, (CUR).x);                                     \
        v1 = fmaf(v1, d1, (CUR).y);                                     \
        const float s0 = (v0 > 0.5f) ? 1.0f : 0.0f;                     \
        const float s1 = (v1 > 0.5f) ? 1.0f : 0.0f;                     \
        v0 = fmaf(s0, -0.5f, v0);                                       \
        v1 = fmaf(s1, -0.5f, v1);                                       \
        __stcs(op + t * GROUPS2, make_float2(s0, s1));                  \
    } while (0)

    // Steady state: 248 iters = 31 * 8; unroll-8 keeps the ring index a
    // compile-time constant (pure registers).
#pragma unroll 8
    for (int t = 0; t < T_STEPS - PF; t++) {
        const float2 cur = buf[t & (PF - 1)];
        buf[t & (PF - 1)] = __ldcs(xp + (t + PF) * GROUPS2);
        PLIF_STEP(cur);
    }

    // Epilogue: drain the ring, no further loads.
#pragma unroll
    for (int t = T_STEPS - PF; t < T_STEPS; t++) {
        const float2 cur = buf[t & (PF - 1)];
        PLIF_STEP(cur);
    }
#undef PLIF_STEP
}

extern "C" void kernel_launch(void* const* d_in, const int* in_sizes, int n_in,
                              void* d_out, int out_size)
{
    const float* x  = (const float*)d_in[0];        // [128, 256, 2048]
    const float* dp = (const float*)d_in[1];        // [2048]
    float*       o  = (float*)d_out;                // [128, 256, 2048]

    const int total_threads = 128 * GROUPS2;         // 131072
    const int block = 256;
    const int grid  = total_threads / block;         // 512
    plif_scan_kernel<<<grid, block>>>(x, dp, o);
}

// round 7
// speedup vs baseline: 1.0419x; 1.0394x over previous
#include <cuda_runtime.h>
#include <cuda_bf16.h>
#include <math.h>

// PLIF neuron scan: x[B,T,C] -> spikes[B,T,C]
//   v = v*sigmoid(decay_param[c]) + x[b,t,c]; s = (v > 0.5); v -= 0.5*s
// B=128, T=256, C=2048.
//
// R7: DRAM row-locality experiment. One block = one full batch row:
// 512 threads x float4 = 2048 channels = the whole 8KB row. Each block's
// read stream and write stream are perfectly SEQUENTIAL 2MB walks
// (vs R1's 1024 interleaved 4KB-granule 8KB-strided streams chip-wide).
// grid=128 -> single wave, zero tail imbalance; cost = 20/148 SMs idle.
// Evidence basis: R1/R4/R5/R6 all converge at DRAM 77+-1.5% across
// occupancy 20-40%, PF 8-16, block 128-256 -> limiter is DRAM-side
// access-pattern efficiency, not latency hiding.

#define T_STEPS 256
#define C_CH    2048
#define GROUPS  (C_CH / 4)   // 512 float4 groups = one full row per block
#define PF      8            // prefetch depth (proven optimal R1 vs R5)

static_assert((T_STEPS - PF) % PF == 0, "steady loop must be multiple of PF");

__global__ __launch_bounds__(512, 1)   // 128-reg cap; body ~62 regs
void plif_scan_kernel(const float* __restrict__ x,
                      const float* __restrict__ decay_param,
                      float* __restrict__ out)
{
    const int g = threadIdx.x;           // float4 group within C (0..511)
    const int b = blockIdx.x;            // batch row (0..127)

    // Per-channel decay = sigmoid(decay_param). Computed once; IEEE expf to
    // avoid compounded drift over 256 recurrence steps.
    const float4 dp = reinterpret_cast<const float4*>(decay_param)[g];
    const float d0 = 1.0f / (1.0f + expf(-dp.x));
    const float d1 = 1.0f / (1.0f + expf(-dp.y));
    const float d2 = 1.0f / (1.0f + expf(-dp.z));
    const float d3 = 1.0f / (1.0f + expf(-dp.w));

    const float4* xp = reinterpret_cast<const float4*>(x)
                     + (size_t)b * (T_STEPS * GROUPS) + g;
    float4*       op = reinterpret_cast<float4*>(out)
                     + (size_t)b * (T_STEPS * GROUPS) + g;

    float v0 = 0.0f, v1 = 0.0f, v2 = 0.0f, v3 = 0.0f;

    // Prime the ring: PF independent in-flight LDG.128 per thread.
    float4 buf[PF];
#pragma unroll
    for (int i = 0; i < PF; i++)
        buf[i] = __ldcs(xp + i * GROUPS);

#define PLIF_STEP(CUR)                                                  \
    do {                                                                \
        v0 = fmaf(v0, d0, (CUR).x);                                     \
        v1 = fmaf(v1, d1, (CUR).y);                                     \
        v2 = fmaf(v2, d2, (CUR).z);                                     \
        v3 = fmaf(v3, d3, (CUR).w);                                     \
        const float s0 = (v0 > 0.5f) ? 1.0f : 0.0f;                     \
        const float s1 = (v1 > 0.5f) ? 1.0f : 0.0f;                     \
        const float s2 = (v2 > 0.5f) ? 1.0f : 0.0f;                     \
        const float s3 = (v3 > 0.5f) ? 1.0f : 0.0f;                     \
        v0 = fmaf(s0, -0.5f, v0);                                       \
        v1 = fmaf(s1, -0.5f, v1);                                       \
        v2 = fmaf(s2, -0.5f, v2);                                       \
        v3 = fmaf(s3, -0.5f, v3);                                       \
        __stcs(op + t * GROUPS, make_float4(s0, s1, s2, s3));           \
    } while (0)

    // Steady state: 248 iters = 31 * 8; unroll-8 keeps the ring index a
    // compile-time constant (pure registers).
#pragma unroll 8
    for (int t = 0; t < T_STEPS - PF; t++) {
        const float4 cur = buf[t & (PF - 1)];
        buf[t & (PF - 1)] = __ldcs(xp + (t + PF) * GROUPS);
        PLIF_STEP(cur);
    }

    // Epilogue: drain the ring, no further loads.
#pragma unroll
    for (int t = T_STEPS - PF; t < T_STEPS; t++) {
        const float4 cur = buf[t & (PF - 1)];
        PLIF_STEP(cur);
    }
#undef PLIF_STEP
}

extern "C" void kernel_launch(void* const* d_in, const int* in_sizes, int n_in,
                              void* d_out, int out_size)
{
    const float* x  = (const float*)d_in[0];        // [128, 256, 2048]
    const float* dp = (const float*)d_in[1];        // [2048]
    float*       o  = (float*)d_out;                // [128, 256, 2048]

    plif_scan_kernel<<<128, 512>>>(x, dp, o);       // one block per batch row
}